// round 3
// baseline (speedup 1.0000x reference)
#include <cuda_runtime.h>

// AR(3), 2 dims, diagonal alpha. 4096 trials x 8192 steps.
// Chunked linear-recurrence decomposition:
//   K1: zero-init chunk finals r_c   (parallel over 131072 chunk-units)
//   K2: propagate chunk initial states s_{c+1} = M^L s_c + r_c  (8192 chains)
//   K3: re-run each chunk from true s_c, write out  (parallel)
//
// noise'[s,0] = s0*n0 + k0,  noise'[s,1] = rho*s1*n0 + sqrt(1-rho^2)*s1*n1 + k1
// k_d folds mu and xmu so the recurrence runs on un-centered x directly.

#define TRIALS 4096
#define STEPS  8192
#define NNOISE (STEPS - 3)        // 8189
#define C      32                 // chunks per trial
#define L      256                // noise steps per chunk
#define U      64                 // (trial,chunk) units per block
#define T      64                 // time-tile within a chunk
#define NTH    128
#define PITCH  (2*U + 2)          // 130 floats: conflict-free phase-2 reads
#define NUNITS (TRIALS * C)       // 131072

__device__ float g_r[NUNITS * 6];   // zero-init chunk finals  [unit][d][3]
__device__ float g_s[NUNITS * 6];   // chunk initial states    [unit][d][3]

struct Params {
    float a00,a01,a10,a11,a20,a21, s0,s1,c10,c11,k0,k1;
};

__device__ __forceinline__ Params load_params(
    const float* __restrict__ alpha, const float* __restrict__ xmu,
    const float* __restrict__ sigma, const float* __restrict__ rho_p,
    const float* __restrict__ mu)
{
    Params p;
    p.a00 = alpha[0]; p.a01 = alpha[1];
    p.a10 = alpha[2]; p.a11 = alpha[3];
    p.a20 = alpha[4]; p.a21 = alpha[5];
    p.s0 = sigma[0];  p.s1 = sigma[1];
    float rho = rho_p[0];
    p.c10 = rho * p.s1;
    p.c11 = sqrtf(1.0f - rho * rho) * p.s1;
    p.k0  = mu[0] + xmu[0] * (1.0f - p.a00 - p.a10 - p.a20);
    p.k1  = mu[1] + xmu[1] * (1.0f - p.a01 - p.a11 - p.a21);
    return p;
}

// ---------------- K1: zero-init chunk finals ----------------
__global__ __launch_bounds__(NTH)
void k1_chunk_finals(const float* __restrict__ alpha, const float* __restrict__ xmu,
                     const float* __restrict__ sigma, const float* __restrict__ rho_p,
                     const float* __restrict__ mu,   const float* __restrict__ normals)
{
    __shared__ float sm[T * PITCH];
    const Params P = load_params(alpha, xmu, sigma, rho_p, mu);

    const int tid   = threadIdx.x;
    const int unit0 = blockIdx.x * U;

    // this thread's recurrence chain: unit = unit0 + (tid>>1), dim = tid&1
    const int mu_   = unit0 + (tid >> 1);
    const int dd    = tid & 1;
    const int mych  = mu_ & (C - 1);
    const int myn   = min(L, NNOISE - mych * L);
    const float aa0 = dd ? P.a01 : P.a00;
    const float aa1 = dd ? P.a11 : P.a10;
    const float aa2 = dd ? P.a21 : P.a20;
    float xs0 = 0.f, xs1 = 0.f, xs2 = 0.f;   // zero initial state

    const int sl   = tid & 63;   // step-in-tile for loading
    const int half = tid >> 6;   // which of the 2 units this pass

    for (int t0 = 0; t0 < L; t0 += T) {
        // phase 1: coalesced load + noise transform -> smem (time-major)
        #pragma unroll 8
        for (int ps = 0; ps < U; ps += 2) {
            const int uu = ps + half;
            const int un = unit0 + uu;
            const int tr = un >> 5;          // /C
            const int ch = un & (C - 1);
            const int nn = min(L, NNOISE - ch * L) - t0;
            if (sl < nn) {
                float2 v = ((const float2*)normals)[tr * NNOISE + ch * L + t0 + sl];
                float e0 = fmaf(P.s0, v.x, P.k0);
                float e1 = fmaf(P.c10, v.x, fmaf(P.c11, v.y, P.k1));
                *(float2*)&sm[sl * PITCH + 2 * uu] = make_float2(e0, e1);
            }
        }
        __syncthreads();

        // phase 2: all 128 threads recur their chain over the tile
        const int jmax = min(T, myn - t0);
        #pragma unroll 4
        for (int j = 0; j < jmax; ++j) {
            float nz = sm[j * PITCH + tid];
            float x  = fmaf(aa2, xs2, fmaf(aa1, xs1, fmaf(aa0, xs0, nz)));
            xs0 = xs1; xs1 = xs2; xs2 = x;
        }
        __syncthreads();
    }

    float* r = g_r + mu_ * 6 + dd * 3;
    r[0] = xs0; r[1] = xs1; r[2] = xs2;
}

// ---------------- K2: propagate chunk initial states ----------------
__global__ __launch_bounds__(256)
void k2_propagate(const float* __restrict__ alpha, const float* __restrict__ x_0,
                  float* __restrict__ out)
{
    const int tid   = blockIdx.x * blockDim.x + threadIdx.x;  // 0..8191
    const int trial = tid >> 1;
    const int d     = tid & 1;
    const float a0 = alpha[0 + d], a1 = alpha[2 + d], a2 = alpha[4 + d];

    // P = M^L, M = [[0,1,0],[0,0,1],[a0,a1,a2]]
    float p00=1,p01=0,p02=0, p10=0,p11=1,p12=0, p20=0,p21=0,p22=1;
    for (int i = 0; i < L; ++i) {
        float q0 = fmaf(a0,p00, fmaf(a1,p10, a2*p20));
        float q1 = fmaf(a0,p01, fmaf(a1,p11, a2*p21));
        float q2 = fmaf(a0,p02, fmaf(a1,p12, a2*p22));
        p00=p10; p01=p11; p02=p12;
        p10=p20; p11=p21; p12=p22;
        p20=q0;  p21=q1;  p22=q2;
    }

    // initial state from x_0 (un-centered), also first 3 outputs verbatim
    float s0 = x_0[trial*6 + 0 + d];
    float s1 = x_0[trial*6 + 2 + d];
    float s2 = x_0[trial*6 + 4 + d];
    out[trial*STEPS*2 + 0 + d] = s0;
    out[trial*STEPS*2 + 2 + d] = s1;
    out[trial*STEPS*2 + 4 + d] = s2;

    #pragma unroll 4
    for (int c = 0; c < C; ++c) {
        const int base = (trial * C + c) * 6 + d * 3;
        g_s[base+0] = s0; g_s[base+1] = s1; g_s[base+2] = s2;
        float r0 = g_r[base+0], r1 = g_r[base+1], r2 = g_r[base+2];
        float n0 = fmaf(p00,s0, fmaf(p01,s1, fmaf(p02,s2, r0)));
        float n1 = fmaf(p10,s0, fmaf(p11,s1, fmaf(p12,s2, r1)));
        float n2 = fmaf(p20,s0, fmaf(p21,s1, fmaf(p22,s2, r2)));
        s0 = n0; s1 = n1; s2 = n2;
    }
}

// ---------------- K3: final pass with true initial states ----------------
__global__ __launch_bounds__(NTH)
void k3_emit(const float* __restrict__ alpha, const float* __restrict__ xmu,
             const float* __restrict__ sigma, const float* __restrict__ rho_p,
             const float* __restrict__ mu,   const float* __restrict__ normals,
             float* __restrict__ out)
{
    __shared__ float sm[T * PITCH];
    const Params P = load_params(alpha, xmu, sigma, rho_p, mu);

    const int tid   = threadIdx.x;
    const int unit0 = blockIdx.x * U;

    const int mu_   = unit0 + (tid >> 1);
    const int dd    = tid & 1;
    const int mych  = mu_ & (C - 1);
    const int myn   = min(L, NNOISE - mych * L);
    const float aa0 = dd ? P.a01 : P.a00;
    const float aa1 = dd ? P.a11 : P.a10;
    const float aa2 = dd ? P.a21 : P.a20;

    const float* s = g_s + mu_ * 6 + dd * 3;
    float xs0 = s[0], xs1 = s[1], xs2 = s[2];

    const int sl   = tid & 63;
    const int half = tid >> 6;

    for (int t0 = 0; t0 < L; t0 += T) {
        // phase 1: load + transform noise
        #pragma unroll 8
        for (int ps = 0; ps < U; ps += 2) {
            const int uu = ps + half;
            const int un = unit0 + uu;
            const int tr = un >> 5;
            const int ch = un & (C - 1);
            const int nn = min(L, NNOISE - ch * L) - t0;
            if (sl < nn) {
                float2 v = ((const float2*)normals)[tr * NNOISE + ch * L + t0 + sl];
                float e0 = fmaf(P.s0, v.x, P.k0);
                float e1 = fmaf(P.c10, v.x, fmaf(P.c11, v.y, P.k1));
                *(float2*)&sm[sl * PITCH + 2 * uu] = make_float2(e0, e1);
            }
        }
        __syncthreads();

        // phase 2: recur, overwrite noise with x in place
        const int jmax = min(T, myn - t0);
        #pragma unroll 4
        for (int j = 0; j < jmax; ++j) {
            float nz = sm[j * PITCH + tid];
            float x  = fmaf(aa2, xs2, fmaf(aa1, xs1, fmaf(aa0, xs0, nz)));
            sm[j * PITCH + tid] = x;
            xs0 = xs1; xs1 = xs2; xs2 = x;
        }
        __syncthreads();

        // phase 3: coalesced flush -> out  (time t = chunk*L + 3 + step)
        #pragma unroll 8
        for (int ps = 0; ps < U; ps += 2) {
            const int uu = ps + half;
            const int un = unit0 + uu;
            const int tr = un >> 5;
            const int ch = un & (C - 1);
            const int nn = min(L, NNOISE - ch * L) - t0;
            if (sl < nn) {
                ((float2*)out)[tr * STEPS + ch * L + 3 + t0 + sl] =
                    *(float2*)&sm[sl * PITCH + 2 * uu];
            }
        }
        __syncthreads();
    }
}

extern "C" void kernel_launch(void* const* d_in, const int* in_sizes, int n_in,
                              void* d_out, int out_size)
{
    const float* alpha   = (const float*)d_in[0];
    const float* xmu     = (const float*)d_in[1];
    const float* sigma   = (const float*)d_in[2];
    const float* rho     = (const float*)d_in[3];
    const float* mu      = (const float*)d_in[4];
    const float* x_0     = (const float*)d_in[5];
    const float* normals = (const float*)d_in[6];
    float* out = (float*)d_out;

    k1_chunk_finals<<<NUNITS / U, NTH>>>(alpha, xmu, sigma, rho, mu, normals);
    k2_propagate<<<TRIALS * 2 / 256, 256>>>(alpha, x_0, out);
    k3_emit<<<NUNITS / U, NTH>>>(alpha, xmu, sigma, rho, mu, normals, out);
}

// round 5
// speedup vs baseline: 3.0789x; 3.0789x over previous
#include <cuda_runtime.h>

// AR(3), 2 dims, diagonal alpha. 4096 trials x 8192 steps.
// One block per trial. Per half-trial (4096 noise steps):
//   A: coalesced load + noise transform -> smem (time-major, conflict-free)
//   B: 128 segments/dim x 32 steps: zero-init local run + transition M^32
//   scan: warp-shuffle affine scan + serial warp-total chain -> true seg states
//   C: re-run segments from true states (exact serial arithmetic in-segment)
//   D: coalesced flush -> out
//
// noise'[s,0] = s0*n0 + k0 ; noise'[s,1] = rho*s1*n0 + sqrt(1-rho^2)*s1*n1 + k1
// k_d folds mu and xmu so the recurrence runs on un-centered x directly.

#define TRIALS 4096
#define STEPS  8192
#define NNOISE (STEPS - 3)     // 8189
#define HALF   4096            // noise steps in half 0 (half 1: 4093)
#define SEG    32
#define NTH    256
#define ROW    257             // smem row pitch (256 data + 1 pad)

__global__ __launch_bounds__(NTH)
void arma_scan(const float* __restrict__ alpha, const float* __restrict__ xmu,
               const float* __restrict__ sigma, const float* __restrict__ rho_p,
               const float* __restrict__ mu,    const float* __restrict__ x_0,
               const float* __restrict__ normals, float* __restrict__ out)
{
    __shared__ float sm[SEG * ROW];          // 32 x 257 floats = 32.9 KB
    __shared__ float swA[2][4][9];           // warp-total matrices
    __shared__ float swb[2][4][3];           // warp-total offsets
    __shared__ float sst[2][4][3];           // warp start states

    const int tid  = threadIdx.x;
    const int d    = tid >> 7;               // dim: warps 0-3 -> d0, 4-7 -> d1
    const int i    = tid & 127;              // segment index within dim
    const int lane = tid & 31;
    const int wd   = (tid >> 5) & 3;         // warp within dim
    const int tr   = blockIdx.x;

    // ---- parameters ----
    const float s0v = sigma[0], s1v = sigma[1];
    const float rho = rho_p[0];
    const float c10 = rho * s1v;
    const float c11 = sqrtf(1.0f - rho * rho) * s1v;
    const float k0  = mu[0] + xmu[0] * (1.0f - alpha[0] - alpha[2] - alpha[4]);
    const float k1  = mu[1] + xmu[1] * (1.0f - alpha[1] - alpha[3] - alpha[5]);
    const float a0  = alpha[0 + d], a1 = alpha[2 + d], a2 = alpha[4 + d];

    const float2* nsrc = (const float2*)normals + (size_t)tr * NNOISE;
    float2*       odst = (float2*)out + (size_t)tr * STEPS;

    // first ORDER outputs = x_0 verbatim
    if (tid < 6) out[(size_t)tr * STEPS * 2 + tid] = x_0[tr * 6 + tid];

    // per-dim serial carry (held by thread i==0 of each dim)
    float cs0 = 0.f, cs1 = 0.f, cs2 = 0.f;
    if (i == 0) {
        cs0 = x_0[tr * 6 + 0 + d];
        cs1 = x_0[tr * 6 + 2 + d];
        cs2 = x_0[tr * 6 + 4 + d];
    }

    for (int h = 0; h < 2; ++h) {
        const int nh    = h ? (NNOISE - HALF) : HALF;   // 4096 / 4093
        const int tbase = h * HALF;

        // ---- phase A: coalesced load + transform -> smem ----
        #pragma unroll 4
        for (int s = tid; s < HALF; s += NTH) {
            if (s < nh) {
                float2 v = nsrc[tbase + s];
                float e0 = fmaf(s0v, v.x, k0);
                float e1 = fmaf(c10, v.x, fmaf(c11, v.y, k1));
                int j = s & (SEG - 1), ii = s >> 5;
                sm[j * ROW + ii]       = e0;
                sm[j * ROW + 128 + ii] = e1;
            }
        }
        __syncthreads();

        // ---- phase B: zero-init local run + transition matrix M^slen ----
        const int slen = min(SEG, max(0, nh - i * SEG));
        float b0 = 0.f, b1 = 0.f, b2 = 0.f;
        float A00=1,A01=0,A02=0, A10=0,A11=1,A12=0, A20=0,A21=0,A22=1;
        {
            const float* np = sm + d * 128 + i;
            #pragma unroll 4
            for (int j = 0; j < slen; ++j) {
                float nz = np[j * ROW];
                float x  = fmaf(a2, b2, fmaf(a1, b1, fmaf(a0, b0, nz)));
                b0 = b1; b1 = b2; b2 = x;
                float r0 = fmaf(a0, A00, fmaf(a1, A10, a2 * A20));
                float r1 = fmaf(a0, A01, fmaf(a1, A11, a2 * A21));
                float r2 = fmaf(a0, A02, fmaf(a1, A12, a2 * A22));
                A00=A10; A01=A11; A02=A12;
                A10=A20; A11=A21; A12=A22;
                A20=r0;  A21=r1;  A22=r2;
            }
        }

        // ---- intra-warp inclusive affine scan (self = self o prev) ----
        #pragma unroll
        for (int k = 1; k <= 16; k <<= 1) {
            float pA00=__shfl_up_sync(0xffffffffu,A00,k);
            float pA01=__shfl_up_sync(0xffffffffu,A01,k);
            float pA02=__shfl_up_sync(0xffffffffu,A02,k);
            float pA10=__shfl_up_sync(0xffffffffu,A10,k);
            float pA11=__shfl_up_sync(0xffffffffu,A11,k);
            float pA12=__shfl_up_sync(0xffffffffu,A12,k);
            float pA20=__shfl_up_sync(0xffffffffu,A20,k);
            float pA21=__shfl_up_sync(0xffffffffu,A21,k);
            float pA22=__shfl_up_sync(0xffffffffu,A22,k);
            float pb0 =__shfl_up_sync(0xffffffffu,b0 ,k);
            float pb1 =__shfl_up_sync(0xffffffffu,b1 ,k);
            float pb2 =__shfl_up_sync(0xffffffffu,b2 ,k);
            if (lane >= k) {
                // matrix composition first (reads only A*, pA*)
                float n00 = fmaf(A00,pA00, fmaf(A01,pA10, A02*pA20));
                float n01 = fmaf(A00,pA01, fmaf(A01,pA11, A02*pA21));
                float n02 = fmaf(A00,pA02, fmaf(A01,pA12, A02*pA22));
                float n10 = fmaf(A10,pA00, fmaf(A11,pA10, A12*pA20));
                float n11 = fmaf(A10,pA01, fmaf(A11,pA11, A12*pA21));
                float n12 = fmaf(A10,pA02, fmaf(A11,pA12, A12*pA22));
                float n20 = fmaf(A20,pA00, fmaf(A21,pA10, A22*pA20));
                float n21 = fmaf(A20,pA01, fmaf(A21,pA11, A22*pA21));
                float n22 = fmaf(A20,pA02, fmaf(A21,pA12, A22*pA22));
                float nb0 = fmaf(A00,pb0, fmaf(A01,pb1, fmaf(A02,pb2, b0)));
                float nb1 = fmaf(A10,pb0, fmaf(A11,pb1, fmaf(A12,pb2, b1)));
                float nb2 = fmaf(A20,pb0, fmaf(A21,pb1, fmaf(A22,pb2, b2)));
                A00=n00; A01=n01; A02=n02;
                A10=n10; A11=n11; A12=n12;
                A20=n20; A21=n21; A22=n22;
                b0=nb0; b1=nb1; b2=nb2;
            }
        }
        if (lane == 31) {
            float* Aw = swA[d][wd]; float* bw = swb[d][wd];
            Aw[0]=A00; Aw[1]=A01; Aw[2]=A02;
            Aw[3]=A10; Aw[4]=A11; Aw[5]=A12;
            Aw[6]=A20; Aw[7]=A21; Aw[8]=A22;
            bw[0]=b0; bw[1]=b1; bw[2]=b2;
        }
        __syncthreads();

        // ---- serial warp-total chain (one thread per dim) ----
        if (i == 0) {
            float t0c = cs0, t1c = cs1, t2c = cs2;
            #pragma unroll
            for (int w = 0; w < 4; ++w) {
                sst[d][w][0]=t0c; sst[d][w][1]=t1c; sst[d][w][2]=t2c;
                const float* Aw = swA[d][w]; const float* bw = swb[d][w];
                float u0 = fmaf(Aw[0],t0c, fmaf(Aw[1],t1c, fmaf(Aw[2],t2c, bw[0])));
                float u1 = fmaf(Aw[3],t0c, fmaf(Aw[4],t1c, fmaf(Aw[5],t2c, bw[1])));
                float u2 = fmaf(Aw[6],t0c, fmaf(Aw[7],t1c, fmaf(Aw[8],t2c, bw[2])));
                t0c=u0; t1c=u1; t2c=u2;
            }
            cs0=t0c; cs1=t1c; cs2=t2c;    // carry to next half
        }
        __syncthreads();

        // ---- per-lane exclusive prefix -> true segment initial state ----
        float w0 = sst[d][wd][0], w1 = sst[d][wd][1], w2 = sst[d][wd][2];
        float pA00=__shfl_up_sync(0xffffffffu,A00,1);
        float pA01=__shfl_up_sync(0xffffffffu,A01,1);
        float pA02=__shfl_up_sync(0xffffffffu,A02,1);
        float pA10=__shfl_up_sync(0xffffffffu,A10,1);
        float pA11=__shfl_up_sync(0xffffffffu,A11,1);
        float pA12=__shfl_up_sync(0xffffffffu,A12,1);
        float pA20=__shfl_up_sync(0xffffffffu,A20,1);
        float pA21=__shfl_up_sync(0xffffffffu,A21,1);
        float pA22=__shfl_up_sync(0xffffffffu,A22,1);
        float pb0 =__shfl_up_sync(0xffffffffu,b0 ,1);
        float pb1 =__shfl_up_sync(0xffffffffu,b1 ,1);
        float pb2 =__shfl_up_sync(0xffffffffu,b2 ,1);
        float si0, si1, si2;
        if (lane == 0) { si0=w0; si1=w1; si2=w2; }
        else {
            si0 = fmaf(pA00,w0, fmaf(pA01,w1, fmaf(pA02,w2, pb0)));
            si1 = fmaf(pA10,w0, fmaf(pA11,w1, fmaf(pA12,w2, pb1)));
            si2 = fmaf(pA20,w0, fmaf(pA21,w1, fmaf(pA22,w2, pb2)));
        }

        // ---- phase C: re-run from true state, in-place ----
        {
            float* wp = sm + d * 128 + i;
            #pragma unroll 4
            for (int j = 0; j < slen; ++j) {
                float nz = wp[j * ROW];
                float x  = fmaf(a2, si2, fmaf(a1, si1, fmaf(a0, si0, nz)));
                wp[j * ROW] = x;
                si0 = si1; si1 = si2; si2 = x;
            }
        }
        __syncthreads();

        // ---- phase D: coalesced flush -> out (time t = tbase + 3 + s) ----
        #pragma unroll 4
        for (int s = tid; s < HALF; s += NTH) {
            if (s < nh) {
                int j = s & (SEG - 1), ii = s >> 5;
                odst[tbase + 3 + s] =
                    make_float2(sm[j * ROW + ii], sm[j * ROW + 128 + ii]);
            }
        }
        __syncthreads();
    }
}

extern "C" void kernel_launch(void* const* d_in, const int* in_sizes, int n_in,
                              void* d_out, int out_size)
{
    const float* alpha   = (const float*)d_in[0];
    const float* xmu     = (const float*)d_in[1];
    const float* sigma   = (const float*)d_in[2];
    const float* rho     = (const float*)d_in[3];
    const float* mu      = (const float*)d_in[4];
    const float* x_0     = (const float*)d_in[5];
    const float* normals = (const float*)d_in[6];
    float* out = (float*)d_out;

    arma_scan<<<TRIALS, NTH>>>(alpha, xmu, sigma, rho, mu, x_0, normals, out);
}

// round 6
// speedup vs baseline: 3.5266x; 1.1454x over previous
#include <cuda_runtime.h>

// AR(3), 2 dims, diagonal alpha. 4096 trials x 8192 steps.
// One block per trial, 4 tiles of 2048 noise steps. Per tile:
//   A: coalesced load + noise transform -> smem (time-major, conflict-free)
//   B: 128 segments/dim x 16 steps: zero-init local run -> offset b
//   scan: uniform-matrix affine scan (shuffle b only; matrices A^(16*2^k)
//         precomputed once per block in smem) -> true segment start states
//   C: re-run segments from true states (exact serial arithmetic in-segment)
//   D: coalesced flush -> out
//
// noise'[s,0] = s0*n0 + k0 ; noise'[s,1] = rho*s1*n0 + sqrt(1-rho^2)*s1*n1 + k1
// k_d folds mu and xmu so the recurrence runs on un-centered x directly.

#define TRIALS 4096
#define STEPS  8192
#define NNOISE (STEPS - 3)     // 8189
#define TILE   2048
#define NTILES 4               // tiles: 2048,2048,2048,2045
#define SEG    16
#define NTH    256
#define ROW    258             // stride ≡ 2 mod 32 -> conflict-free A/D

__global__ __launch_bounds__(NTH)
void arma_scan(const float* __restrict__ alpha, const float* __restrict__ xmu,
               const float* __restrict__ sigma, const float* __restrict__ rho_p,
               const float* __restrict__ mu,    const float* __restrict__ x_0,
               const float* __restrict__ normals, float* __restrict__ out)
{
    __shared__ float sm[SEG * ROW];          // 16 x 258 floats = 16.5 KB
    __shared__ float swL[2][6][9];           // A^(16*2^k), k=0..5, per dim
    __shared__ float swb[2][4][3];           // warp-total offsets
    __shared__ float sst[2][4][3];           // warp start states

    const int tid  = threadIdx.x;
    const int d    = tid >> 7;               // dim: warps 0-3 -> d0, 4-7 -> d1
    const int i    = tid & 127;              // segment index within dim
    const int lane = tid & 31;
    const int wd   = (tid >> 5) & 3;         // warp within dim
    const int tr   = blockIdx.x;

    // ---- parameters ----
    const float s0v = sigma[0], s1v = sigma[1];
    const float rho = rho_p[0];
    const float c10 = rho * s1v;
    const float c11 = sqrtf(1.0f - rho * rho) * s1v;
    const float k0  = mu[0] + xmu[0] * (1.0f - alpha[0] - alpha[2] - alpha[4]);
    const float k1  = mu[1] + xmu[1] * (1.0f - alpha[1] - alpha[3] - alpha[5]);
    const float a0  = alpha[0 + d], a1 = alpha[2 + d], a2 = alpha[4 + d];

    const float2* nsrc = (const float2*)normals + (size_t)tr * NNOISE;
    float2*       odst = (float2*)out + (size_t)tr * STEPS;

    // first ORDER outputs = x_0 verbatim
    if (tid < 6) out[(size_t)tr * STEPS * 2 + tid] = x_0[tr * 6 + tid];

    // per-dim serial carry (thread i==0 of each dim)
    float cs0 = 0.f, cs1 = 0.f, cs2 = 0.f;
    if (i == 0) {
        cs0 = x_0[tr * 6 + 0 + d];
        cs1 = x_0[tr * 6 + 2 + d];
        cs2 = x_0[tr * 6 + 4 + d];

        // ---- one-time: level matrices A^(16*2^k) -> smem ----
        // M row-shift: M^{n+1} rows = (row1, row2, a0*row0+a1*row1+a2*row2)
        float m0=1,m1=0,m2=0, m3=0,m4=1,m5=0, m6=0,m7=0,m8=1;
        #pragma unroll
        for (int j = 0; j < SEG; ++j) {
            float r0 = fmaf(a0, m0, fmaf(a1, m3, a2 * m6));
            float r1 = fmaf(a0, m1, fmaf(a1, m4, a2 * m7));
            float r2 = fmaf(a0, m2, fmaf(a1, m5, a2 * m8));
            m0=m3; m1=m4; m2=m5;  m3=m6; m4=m7; m5=m8;  m6=r0; m7=r1; m8=r2;
        }
        float* L = swL[d][0];
        L[0]=m0; L[1]=m1; L[2]=m2; L[3]=m3; L[4]=m4; L[5]=m5; L[6]=m6; L[7]=m7; L[8]=m8;
        #pragma unroll
        for (int k = 1; k < 6; ++k) {
            float c0 = fmaf(m0,m0, fmaf(m1,m3, m2*m6));
            float c1 = fmaf(m0,m1, fmaf(m1,m4, m2*m7));
            float c2 = fmaf(m0,m2, fmaf(m1,m5, m2*m8));
            float c3 = fmaf(m3,m0, fmaf(m4,m3, m5*m6));
            float c4 = fmaf(m3,m1, fmaf(m4,m4, m5*m7));
            float c5 = fmaf(m3,m2, fmaf(m4,m5, m5*m8));
            float c6 = fmaf(m6,m0, fmaf(m7,m3, m8*m6));
            float c7 = fmaf(m6,m1, fmaf(m7,m4, m8*m7));
            float c8 = fmaf(m6,m2, fmaf(m7,m5, m8*m8));
            m0=c0; m1=c1; m2=c2; m3=c3; m4=c4; m5=c5; m6=c6; m7=c7; m8=c8;
            float* Lk = swL[d][k];
            Lk[0]=m0; Lk[1]=m1; Lk[2]=m2; Lk[3]=m3; Lk[4]=m4;
            Lk[5]=m5; Lk[6]=m6; Lk[7]=m7; Lk[8]=m8;
        }
    }

    for (int h = 0; h < NTILES; ++h) {
        const int tbase = h * TILE;
        const int nh    = min(TILE, NNOISE - tbase);   // 2048 / 2045

        // ---- phase A: coalesced load + transform -> smem ----
        #pragma unroll 8
        for (int s = tid; s < TILE; s += NTH) {
            if (s < nh) {
                float2 v = nsrc[tbase + s];
                float e0 = fmaf(s0v, v.x, k0);
                float e1 = fmaf(c10, v.x, fmaf(c11, v.y, k1));
                int j = s & (SEG - 1), ii = s >> 4;
                sm[j * ROW + ii]       = e0;
                sm[j * ROW + 128 + ii] = e1;
            }
        }
        __syncthreads();

        // ---- phase B: zero-init local run -> offset b ----
        const int slen = min(SEG, nh - i * SEG);       // always >= 1
        float b0 = 0.f, b1 = 0.f, b2 = 0.f;
        {
            const float* np = sm + d * 128 + i;
            #pragma unroll 4
            for (int j = 0; j < slen; ++j) {
                float nz = np[j * ROW];
                float x  = fmaf(a2, b2, fmaf(a1, b1, fmaf(a0, b0, nz)));
                b0 = b1; b1 = b2; b2 = x;
            }
        }

        // ---- uniform-matrix inclusive b-scan (shuffle b only) ----
        #pragma unroll
        for (int k = 0; k < 5; ++k) {
            const int sh = 1 << k;
            float pb0 = __shfl_up_sync(0xffffffffu, b0, sh);
            float pb1 = __shfl_up_sync(0xffffffffu, b1, sh);
            float pb2 = __shfl_up_sync(0xffffffffu, b2, sh);
            if (lane >= sh) {
                const float* L = swL[d][k];
                b0 = fmaf(L[0], pb0, fmaf(L[1], pb1, fmaf(L[2], pb2, b0)));
                b1 = fmaf(L[3], pb0, fmaf(L[4], pb1, fmaf(L[5], pb2, b1)));
                b2 = fmaf(L[6], pb0, fmaf(L[7], pb1, fmaf(L[8], pb2, b2)));
            }
        }
        if (lane == 31) {
            swb[d][wd][0] = b0; swb[d][wd][1] = b1; swb[d][wd][2] = b2;
        }
        __syncthreads();

        // ---- serial warp-total chain (one thread per dim, A^512 uniform) ----
        if (i == 0) {
            const float* L5 = swL[d][5];
            float t0 = cs0, t1 = cs1, t2 = cs2;
            #pragma unroll
            for (int w = 0; w < 4; ++w) {
                sst[d][w][0] = t0; sst[d][w][1] = t1; sst[d][w][2] = t2;
                const float* bw = swb[d][w];
                float u0 = fmaf(L5[0],t0, fmaf(L5[1],t1, fmaf(L5[2],t2, bw[0])));
                float u1 = fmaf(L5[3],t0, fmaf(L5[4],t1, fmaf(L5[5],t2, bw[1])));
                float u2 = fmaf(L5[6],t0, fmaf(L5[7],t1, fmaf(L5[8],t2, bw[2])));
                t0 = u0; t1 = u1; t2 = u2;
            }
            cs0 = t0; cs1 = t1; cs2 = t2;   // carry to next tile
        }
        __syncthreads();

        // ---- per-lane start state: A^(16*lane)*w + exclusive b ----
        float v0 = sst[d][wd][0], v1 = sst[d][wd][1], v2 = sst[d][wd][2];
        #pragma unroll
        for (int k = 0; k < 5; ++k) {
            if (lane & (1 << k)) {
                const float* L = swL[d][k];
                float t0 = fmaf(L[0], v0, fmaf(L[1], v1, L[2] * v2));
                float t1 = fmaf(L[3], v0, fmaf(L[4], v1, L[5] * v2));
                float t2 = fmaf(L[6], v0, fmaf(L[7], v1, L[8] * v2));
                v0 = t0; v1 = t1; v2 = t2;
            }
        }
        float pb0 = __shfl_up_sync(0xffffffffu, b0, 1);
        float pb1 = __shfl_up_sync(0xffffffffu, b1, 1);
        float pb2 = __shfl_up_sync(0xffffffffu, b2, 1);
        float si0 = lane ? (v0 + pb0) : v0;
        float si1 = lane ? (v1 + pb1) : v1;
        float si2 = lane ? (v2 + pb2) : v2;

        // ---- phase C: re-run from true state, in-place ----
        {
            float* wp = sm + d * 128 + i;
            #pragma unroll 4
            for (int j = 0; j < slen; ++j) {
                float nz = wp[j * ROW];
                float x  = fmaf(a2, si2, fmaf(a1, si1, fmaf(a0, si0, nz)));
                wp[j * ROW] = x;
                si0 = si1; si1 = si2; si2 = x;
            }
        }
        __syncthreads();

        // ---- phase D: coalesced flush -> out (time t = tbase + 3 + s) ----
        #pragma unroll 8
        for (int s = tid; s < TILE; s += NTH) {
            if (s < nh) {
                int j = s & (SEG - 1), ii = s >> 4;
                odst[tbase + 3 + s] =
                    make_float2(sm[j * ROW + ii], sm[j * ROW + 128 + ii]);
            }
        }
        __syncthreads();
    }
}

extern "C" void kernel_launch(void* const* d_in, const int* in_sizes, int n_in,
                              void* d_out, int out_size)
{
    const float* alpha   = (const float*)d_in[0];
    const float* xmu     = (const float*)d_in[1];
    const float* sigma   = (const float*)d_in[2];
    const float* rho     = (const float*)d_in[3];
    const float* mu      = (const float*)d_in[4];
    const float* x_0     = (const float*)d_in[5];
    const float* normals = (const float*)d_in[6];
    float* out = (float*)d_out;

    arma_scan<<<TRIALS, NTH>>>(alpha, xmu, sigma, rho, mu, x_0, normals, out);
}